// round 13
// baseline (speedup 1.0000x reference)
#include <cuda_runtime.h>
#include <cuda_fp16.h>
#include <stdint.h>

#define BB 4
#define NN 2048
#define MM 2048
#define DD 1024
#define HH 16
#define DKK 64
#define RR (BB*NN)

#define EL_X ((size_t)RR*DD)     // 8,388,608
#define EL_W ((size_t)DD*DD)     // 1,048,576

// fp16 arena: 0 X, 1 Y, 2 Q, 3 K, 4 V, 5 T (EL_X each), then 4 weights (EL_W)
__device__ __half g_f16[6*EL_X + 4*EL_W];
__device__ __half g_p16[(size_t)BB*HH*NN*MM];          // unnormalized exp scratch
__device__ float g_rowsum[(size_t)BB*HH*NN];
__device__ uint64_t g_mbits[(size_t)BB*NN*MM/64];      // packed mask bits
__device__ float g_beta_scratch[(size_t)BB*HH*NN*MM];  // fallback only

extern __shared__ char smraw[];

// ---------------------------------------------------------------------------
__device__ __forceinline__ uint32_t smem_u32(const void* p) {
    uint32_t a;
    asm("{ .reg .u64 t; cvta.to.shared.u64 t, %1; cvt.u32.u64 %0, t; }"
        : "=r"(a) : "l"(p));
    return a;
}

#define CP16(s, g) \
    asm volatile("cp.async.cg.shared.global [%0], [%1], 16;" :: "r"(s), "l"(g))
#define CPC() asm volatile("cp.async.commit_group;" ::: "memory")
#define CPW(n) asm volatile("cp.async.wait_group %0;" :: "n"(n) : "memory")

#define LDSM4(r, addr) \
    asm volatile("ldmatrix.sync.aligned.m8n8.x4.shared.b16 {%0,%1,%2,%3}, [%4];" \
        : "=r"((r)[0]), "=r"((r)[1]), "=r"((r)[2]), "=r"((r)[3]) : "r"(addr))
#define LDSM4T(r, addr) \
    asm volatile("ldmatrix.sync.aligned.m8n8.x4.trans.shared.b16 {%0,%1,%2,%3}, [%4];" \
        : "=r"((r)[0]), "=r"((r)[1]), "=r"((r)[2]), "=r"((r)[3]) : "r"(addr))

#define MMA_F16(d, a, b0, b1) \
    asm volatile("mma.sync.aligned.m16n8k16.row.col.f32.f16.f16.f32 " \
        "{%0,%1,%2,%3}, {%4,%5,%6,%7}, {%8,%9}, {%0,%1,%2,%3};" \
        : "+f"((d)[0]), "+f"((d)[1]), "+f"((d)[2]), "+f"((d)[3]) \
        : "r"((a)[0]), "r"((a)[1]), "r"((a)[2]), "r"((a)[3]), "r"(b0), "r"(b1))

__device__ __forceinline__ uint32_t pack16(float x, float y) {
    __half2 v = __floats2half2_rn(x, y);
    return *(uint32_t*)&v;
}

// ---------------------------------------------------------------------------
// fp32 -> fp16 conversions
// ---------------------------------------------------------------------------
__global__ void __launch_bounds__(256) conv_xy(const float* __restrict__ sx,
                                               const float* __restrict__ sy,
                                               __half* __restrict__ dx,
                                               __half* __restrict__ dy, int n4)
{
    int i = blockIdx.x * blockDim.x + threadIdx.x;
    if (i >= n4) return;
    const float* s = blockIdx.y ? sy : sx;
    uint32_t* hp = (uint32_t*)(blockIdx.y ? dy : dx);
    float4 v = ((const float4*)s)[i];
    hp[2*i]   = pack16(v.x, v.y);
    hp[2*i+1] = pack16(v.z, v.w);
}

__global__ void __launch_bounds__(256) conv_w4(const float* __restrict__ s0,
                                               const float* __restrict__ s1,
                                               const float* __restrict__ s2,
                                               const float* __restrict__ s3,
                                               __half* __restrict__ dbase, int n4)
{
    int i = blockIdx.x * blockDim.x + threadIdx.x;
    if (i >= n4) return;
    const float* srcs[4] = {s0, s1, s2, s3};
    const float* s = srcs[blockIdx.y];
    uint32_t* hp = (uint32_t*)(dbase + (size_t)blockIdx.y * EL_W);
    float4 v = ((const float4*)s)[i];
    hp[2*i]   = pack16(v.x, v.y);
    hp[2*i+1] = pack16(v.z, v.w);
}

// pack mask int32 -> bits (bit set <=> mask==1 <=> masked out)
__global__ void __launch_bounds__(256) pack_mask(const int* __restrict__ mask,
                                                 uint64_t* __restrict__ bits,
                                                 int total64)
{
    int i = blockIdx.x * blockDim.x + threadIdx.x;
    if (i >= total64) return;
    const int4* src = (const int4*)(mask + (size_t)i * 64);
    uint64_t w = 0;
    #pragma unroll
    for (int q = 0; q < 16; q++) {
        int4 v = src[q];
        w |= (uint64_t)(v.x == 1) << (q*4 + 0);
        w |= (uint64_t)(v.y == 1) << (q*4 + 1);
        w |= (uint64_t)(v.z == 1) << (q*4 + 2);
        w |= (uint64_t)(v.w == 1) << (q*4 + 3);
    }
    bits[i] = w;
}

// ---------------------------------------------------------------------------
// GEMM core (device inline): C(128x128) = A @ W^T + bias, fp16 in, fp32 acc.
// ---------------------------------------------------------------------------
template<int OUTMODE>
__device__ __forceinline__ void gemm_body(
    const __half* __restrict__ A,
    const __half* __restrict__ W,
    const float* __restrict__ bias,
    float* __restrict__ outF,
    __half* __restrict__ outH,
    int row0, int col0)
{
    __half* sm = (__half*)smraw;
    const int tid  = threadIdx.x;
    const int lane = tid & 31;
    const int wid  = tid >> 5;
    const int wm   = wid & 3;
    const int wn   = wid >> 2;
    const uint32_t sbase = smem_u32(sm);

    float acc[2][8][4];
    #pragma unroll
    for (int i = 0; i < 2; i++)
        #pragma unroll
        for (int j = 0; j < 8; j++)
            #pragma unroll
            for (int q = 0; q < 4; q++) acc[i][j][q] = 0.f;

    #define ISSUE(t) do {                                                      \
        const int k0 = (t) << 6;                                               \
        const uint32_t sA = sbase + (((t) & 1) * 9216) * 2;                    \
        const uint32_t sW = sbase + (18432 + ((t) & 1) * 9216) * 2;            \
        _Pragma("unroll")                                                      \
        for (int i_ = 0; i_ < 4; i_++) {                                       \
            int idx = tid + i_ * 256;                                          \
            int r = idx >> 3, ch = idx & 7;                                    \
            CP16(sA + (r * 72 + ch * 8) * 2,                                   \
                 A + (size_t)(row0 + r) * DD + k0 + ch * 8);                   \
            CP16(sW + (r * 72 + ch * 8) * 2,                                   \
                 W + (size_t)(col0 + r) * DD + k0 + ch * 8);                   \
        }                                                                      \
        CPC();                                                                 \
    } while (0)

    ISSUE(0);
    for (int t = 0; t < 16; t++) {
        if (t + 1 < 16) { ISSUE(t + 1); CPW(1); }
        else            { CPW(0); }
        __syncthreads();
        const uint32_t sA = sbase + ((t & 1) * 9216) * 2;
        const uint32_t sW = sbase + (18432 + (t & 1) * 9216) * 2;
        #pragma unroll
        for (int ks = 0; ks < 4; ks++) {
            uint32_t a[2][4], bq[4][4];
            #pragma unroll
            for (int i = 0; i < 2; i++)
                LDSM4(a[i], sA + ((wm*32 + i*16 + (lane & 15)) * 72
                                  + ks*16 + (lane >> 4) * 8) * 2);
            #pragma unroll
            for (int jj = 0; jj < 4; jj++)
                LDSM4(bq[jj], sW + ((wn*64 + jj*16 + (lane & 15)) * 72
                                    + ks*16 + (lane >> 4) * 8) * 2);
            #pragma unroll
            for (int i = 0; i < 2; i++)
                #pragma unroll
                for (int j = 0; j < 8; j++) {
                    const int jj = j >> 1;
                    uint32_t b0 = (j & 1) ? bq[jj][1] : bq[jj][0];
                    uint32_t b1 = (j & 1) ? bq[jj][3] : bq[jj][2];
                    MMA_F16(acc[i][j], a[i], b0, b1);
                }
        }
        __syncthreads();
    }
    #undef ISSUE

    const int bb = row0 >> 11;
    #pragma unroll
    for (int i = 0; i < 2; i++) {
        const int r  = row0 + wm*32 + i*16 + (lane >> 2);
        const int n  = r & 2047;
        #pragma unroll
        for (int j = 0; j < 8; j++) {
            const int c = col0 + wn*64 + j*8 + (lane & 3)*2;
            const float b0v = __ldg(bias + c), b1v = __ldg(bias + c + 1);
            const float v00 = acc[i][j][0] + b0v, v01 = acc[i][j][1] + b1v;
            const float v10 = acc[i][j][2] + b0v, v11 = acc[i][j][3] + b1v;
            if (OUTMODE == 0) {
                *(float2*)(outF + (size_t)r * DD + c)       = make_float2(v00, v01);
                *(float2*)(outF + (size_t)(r + 8) * DD + c) = make_float2(v10, v11);
            } else {
                const int h = c >> 6, dk = c & 63;
                const size_t a0 = ((((size_t)bb*HH + h)*NN + n)      << 6) + dk;
                const size_t a1 = ((((size_t)bb*HH + h)*NN + (n+8))  << 6) + dk;
                *(uint32_t*)(outH + a0) = pack16(v00, v01);
                *(uint32_t*)(outH + a1) = pack16(v10, v11);
            }
        }
    }
}

// ---------------------------------------------------------------------------
// Q/K/V projections in ONE launch (measured -140us vs 3 launches).
// ---------------------------------------------------------------------------
__global__ void __launch_bounds__(256,2) gemm_qkv(
    const __half* __restrict__ X16, const __half* __restrict__ Y16,
    const __half* __restrict__ W16,
    const float* __restrict__ bq, const float* __restrict__ bk,
    const float* __restrict__ bv,
    __half* __restrict__ Q16, __half* __restrict__ K16, __half* __restrict__ V16)
{
    const int z = blockIdx.z;
    const __half* A   = (z == 0) ? X16 : Y16;
    const __half* W   = W16 + (size_t)z * EL_W;
    const float* bias = (z == 0) ? bq : ((z == 1) ? bk : bv);
    __half* outH      = (z == 0) ? Q16 : ((z == 1) ? K16 : V16);
    gemm_body<1>(A, W, bias, nullptr, outH,
                 blockIdx.y * 128, blockIdx.x * 128);
}

__global__ void __launch_bounds__(256,2) gemm_o(
    const __half* __restrict__ T16, const __half* __restrict__ Wo16,
    const float* __restrict__ bo, float* __restrict__ outF)
{
    gemm_body<0>(T16, Wo16, bo, outF, nullptr,
                 blockIdx.y * 128, blockIdx.x * 128);
}

// ---------------------------------------------------------------------------
// Fused flash middle. smem diet for 2 CTAs/SM:
//   Q 0 (18432), K[2] 18432/36864, V 55296 (single buf), P 73728 (stride 136).
//   Total 108544 B -> 2 CTAs/SM.
// Schedule per m-tile t:
//   syncA; issue {V(t), K(t+1)}; QK(t) on K(t) [ready from prev CPW];
//   exp -> smP + rowsum; CPW(0); syncB; P-store + PV(t).
// ---------------------------------------------------------------------------
#define FQ  0
#define FKb(s) (18432 + (s)*18432)
#define FVb 55296
#define FP  73728
#define FLASH_SMEM 108544

__global__ void __launch_bounds__(256,2) flash_mma(
    const uint64_t* __restrict__ mbits,
    __half* __restrict__ P16,
    const __half* __restrict__ Q,
    const __half* __restrict__ K,
    const __half* __restrict__ V,
    float* __restrict__ rowsum,
    __half* __restrict__ Wt)
{
    char* sm = smraw;
    __shared__ float srow[128];
    const int tid  = threadIdx.x;
    const int lane = tid & 31;
    const int wid  = tid >> 5;
    const int wm   = wid & 3;
    const int wn   = wid >> 2;
    const int z    = blockIdx.y;
    const int b    = z >> 4;
    const int h    = z & 15;
    const int n0   = blockIdx.x * 128;
    const uint32_t sb = smem_u32(sm);
    __half* smP = (__half*)(sm + FP);

    if (tid < 128) srow[tid] = 0.f;

    // ---- prologue: load Q + K(0) (one group), wait.
    {
        const __half* q  = Q + ((size_t)z*NN + n0) * DKK;
        const __half* kp = K + (size_t)z*MM * DKK;
        #pragma unroll
        for (int i = 0; i < 4; i++) {
            int idx = tid + i * 256;
            int r = idx >> 3, ch = idx & 7;
            uint32_t off = (uint32_t)(r * 72 + ch * 8) * 2;
            size_t go = (size_t)r * DKK + ch * 8;
            CP16(sb + FQ + off,     q + go);
            CP16(sb + FKb(0) + off, kp + go);
        }
        CPC(); CPW(0);
    }

    float accO[8][4];
    #pragma unroll
    for (int j = 0; j < 8; j++)
        #pragma unroll
        for (int q = 0; q < 4; q++) accO[j][q] = 0.f;
    float rsum[4] = {0.f, 0.f, 0.f, 0.f};

    const float scl = 0.125f;
    const size_t prow = (size_t)z * NN + n0;

    for (int mt = 0; mt < 16; mt++) {
        __syncthreads();   // syncA: V buf / smP safe to overwrite; prologue loads visible

        // ---- issue V(mt) + K(mt+1) (single group)
        {
            const __half* vp = V + ((size_t)z*MM + mt*128) * DKK;
            const __half* kn = K + ((size_t)z*MM + ((mt+1) & 15)*128) * DKK;
            const int kbuf = (mt + 1) & 1;
            const bool havek = (mt < 15);
            #pragma unroll
            for (int i = 0; i < 4; i++) {
                int idx = tid + i * 256;
                int r = idx >> 3, ch = idx & 7;
                uint32_t off = (uint32_t)(r * 72 + ch * 8) * 2;
                size_t go = (size_t)r * DKK + ch * 8;
                CP16(sb + FVb + off, vp + go);
                if (havek) CP16(sb + FKb(kbuf) + off, kn + go);
            }
            CPC();
        }

        // ---- QK^T on K(mt) (resident)
        float acc[2][8][4];
        #pragma unroll
        for (int i = 0; i < 2; i++)
            #pragma unroll
            for (int j = 0; j < 8; j++)
                #pragma unroll
                for (int q = 0; q < 4; q++) acc[i][j][q] = 0.f;

        const uint32_t sK = sb + FKb(mt & 1);
        #pragma unroll
        for (int ks = 0; ks < 4; ks++) {
            uint32_t a[2][4], bq[4][4];
            #pragma unroll
            for (int i = 0; i < 2; i++)
                LDSM4(a[i], sb + FQ + ((wm*32 + i*16 + (lane & 15)) * 72
                                       + ks*16 + (lane >> 4) * 8) * 2);
            #pragma unroll
            for (int jj = 0; jj < 4; jj++)
                LDSM4(bq[jj], sK + ((wn*64 + jj*16 + (lane & 15)) * 72
                                    + ks*16 + (lane >> 4) * 8) * 2);
            #pragma unroll
            for (int i = 0; i < 2; i++)
                #pragma unroll
                for (int j = 0; j < 8; j++) {
                    const int jj = j >> 1;
                    uint32_t b0 = (j & 1) ? bq[jj][1] : bq[jj][0];
                    uint32_t b1 = (j & 1) ? bq[jj][3] : bq[jj][2];
                    MMA_F16(acc[i][j], a[i], b0, b1);
                }
        }

        // ---- exp epilogue with packed mask bits
        const int m0 = mt * 128;
        #pragma unroll
        for (int i = 0; i < 2; i++) {
            const int r0 = wm*32 + i*16 + (lane >> 2);
            const size_t rowg = (size_t)b*NN + n0 + r0;
            const uint64_t w0 = mbits[rowg*32       + mt*2 + wn];
            const uint64_t w1 = mbits[(rowg + 8)*32 + mt*2 + wn];
            #pragma unroll
            for (int j = 0; j < 8; j++) {
                const int cl = wn*64 + j*8 + (lane & 3)*2;
                const int p  = j*8 + (lane & 3)*2;
                float e00 = ((w0 >> p)     & 1) ? 0.f : __expf(acc[i][j][0] * scl);
                float e01 = ((w0 >> (p+1)) & 1) ? 0.f : __expf(acc[i][j][1] * scl);
                float e10 = ((w1 >> p)     & 1) ? 0.f : __expf(acc[i][j][2] * scl);
                float e11 = ((w1 >> (p+1)) & 1) ? 0.f : __expf(acc[i][j][3] * scl);
                rsum[i*2+0] += e00 + e01;
                rsum[i*2+1] += e10 + e11;
                *(__half2*)(smP + r0*136 + cl)     = __floats2half2_rn(e00, e01);
                *(__half2*)(smP + (r0+8)*136 + cl) = __floats2half2_rn(e10, e11);
            }
        }

        CPW(0);            // V(mt) + K(mt+1) complete
        __syncthreads();   // syncB: smP + V visible to all

        // ---- P smem -> gmem scratch (coalesced)
        #pragma unroll
        for (int it = 0; it < 8; it++) {
            int idx = tid + it * 256;
            int r = idx >> 4, q = idx & 15;
            *(uint4*)(P16 + (prow + r) * MM + m0 + q*8) =
                *(const uint4*)(smP + r*136 + q*8);
        }

        // ---- O += P x V
        #pragma unroll
        for (int ks = 0; ks < 8; ks++) {
            uint32_t a[4], bq[4][4];
            LDSM4(a, sb + FP + ((wid*16 + (lane & 15)) * 136
                                + ks*16 + (lane >> 4) * 8) * 2);
            #pragma unroll
            for (int jj = 0; jj < 4; jj++)
                LDSM4T(bq[jj], sb + FVb + ((ks*16 + ((lane >> 3) & 1)*8 + (lane & 7)) * 72
                                           + jj*16 + (lane >> 4) * 8) * 2);
            #pragma unroll
            for (int j = 0; j < 8; j++) {
                const int jj = j >> 1;
                uint32_t b0 = (j & 1) ? bq[jj][2] : bq[jj][0];
                uint32_t b1 = (j & 1) ? bq[jj][3] : bq[jj][1];
                MMA_F16(accO[j], a, b0, b1);
            }
        }
    }

    // ---- rowsum reduce
    #pragma unroll
    for (int k = 0; k < 4; k++) {
        rsum[k] += __shfl_xor_sync(0xffffffffu, rsum[k], 1);
        rsum[k] += __shfl_xor_sync(0xffffffffu, rsum[k], 2);
    }
    __syncthreads();
    if ((lane & 3) == 0) {
        #pragma unroll
        for (int k = 0; k < 4; k++) {
            const int rl = wm*32 + (k >> 1)*16 + (k & 1)*8 + (lane >> 2);
            atomicAdd(&srow[rl], rsum[k]);
        }
    }
    __syncthreads();
    if (tid < 128) rowsum[prow + tid] = srow[tid];

    // ---- normalize O, write wt (b,n,h,dk) fp16
    const int rl = wid*16 + (lane >> 2);
    const float inv0 = 1.0f / srow[rl];
    const float inv1 = 1.0f / srow[rl + 8];
    const int n = n0 + rl;
    #pragma unroll
    for (int j = 0; j < 8; j++) {
        const int dk = j*8 + (lane & 3)*2;
        const size_t a0 = ((((size_t)b*NN + n)     * HH + h) << 6) + dk;
        const size_t a1 = ((((size_t)b*NN + n + 8) * HH + h) << 6) + dk;
        *(uint32_t*)(Wt + a0) = pack16(accO[j][0]*inv0, accO[j][1]*inv0);
        *(uint32_t*)(Wt + a1) = pack16(accO[j][2]*inv1, accO[j][3]*inv1);
    }
}

// ---------------------------------------------------------------------------
// beta = P16 * (1/rowsum), fp32 out. One block per row (high occupancy, 0 smem).
// ---------------------------------------------------------------------------
__global__ void __launch_bounds__(256) norm_beta(const __half* __restrict__ P16,
                                                 const float* __restrict__ rowsum,
                                                 float* __restrict__ beta)
{
    const size_t row = blockIdx.x;
    const float inv = 1.0f / __ldg(rowsum + row);
    const __half* src = P16 + row * MM;
    float* dst = beta + row * MM;
    const int t = threadIdx.x;
    uint4 v = *(const uint4*)(src + t * 8);
    const __half2* h2 = (const __half2*)&v;
    float4 o0, o1;
    float2 f;
    f = __half22float2(h2[0]); o0.x = f.x*inv; o0.y = f.y*inv;
    f = __half22float2(h2[1]); o0.z = f.x*inv; o0.w = f.y*inv;
    f = __half22float2(h2[2]); o1.x = f.x*inv; o1.y = f.y*inv;
    f = __half22float2(h2[3]); o1.z = f.x*inv; o1.w = f.y*inv;
    *(float4*)(dst + t*8)     = o0;
    *(float4*)(dst + t*8 + 4) = o1;
}

// ============================================================================
extern "C" void kernel_launch(void* const* d_in, const int* in_sizes, int n_in,
                              void* d_out, int out_size)
{
    const float* X    = (const float*)d_in[0];
    const float* Y    = (const float*)d_in[1];
    const int*   mask = (const int*)  d_in[2];
    const float* Wq   = (const float*)d_in[3];
    const float* bq   = (const float*)d_in[4];
    const float* Wk   = (const float*)d_in[5];
    const float* bk   = (const float*)d_in[6];
    const float* Wv   = (const float*)d_in[7];
    const float* bv   = (const float*)d_in[8];
    const float* Wo   = (const float*)d_in[9];
    const float* bo   = (const float*)d_in[10];
    float* out = (float*)d_out;

    const size_t ATTN = (size_t)BB * NN * DD;
    const size_t BETA = (size_t)BB * HH * NN * MM;

    void *fp_, *bsp_, *rsp_, *p16_, *mb_;
    cudaGetSymbolAddress(&fp_, g_f16);
    cudaGetSymbolAddress(&bsp_, g_beta_scratch);
    cudaGetSymbolAddress(&rsp_, g_rowsum);
    cudaGetSymbolAddress(&p16_, g_p16);
    cudaGetSymbolAddress(&mb_, g_mbits);
    __half* f16 = (__half*)fp_;
    __half* P16 = (__half*)p16_;
    float* rowsum = (float*)rsp_;
    uint64_t* mbits = (uint64_t*)mb_;

    __half* X16 = f16 + 0*EL_X;
    __half* Y16 = f16 + 1*EL_X;
    __half* Q16 = f16 + 2*EL_X;
    __half* K16 = f16 + 3*EL_X;
    __half* V16 = f16 + 4*EL_X;
    __half* T16 = f16 + 5*EL_X;
    __half* W16 = f16 + 6*EL_X;      // 4 weights contiguous: Wq,Wk,Wv,Wo

    float* beta = ((size_t)out_size >= ATTN + BETA) ? (out + ATTN)
                                                    : (float*)bsp_;

    // side stream + events created once, on the first (non-captured) call
    static cudaStream_t s2 = nullptr;
    static cudaEvent_t ev1 = nullptr, ev2 = nullptr;
    if (!s2) {
        cudaStreamCreateWithFlags(&s2, cudaStreamNonBlocking);
        cudaEventCreateWithFlags(&ev1, cudaEventDisableTiming);
        cudaEventCreateWithFlags(&ev2, cudaEventDisableTiming);
    }

    const int SMP = 73728;
    cudaFuncSetAttribute(gemm_qkv,  cudaFuncAttributeMaxDynamicSharedMemorySize, SMP);
    cudaFuncSetAttribute(gemm_o,    cudaFuncAttributeMaxDynamicSharedMemorySize, SMP);
    cudaFuncSetAttribute(flash_mma, cudaFuncAttributeMaxDynamicSharedMemorySize, FLASH_SMEM);

    const int n4x = (int)(EL_X / 4);
    const int n4w = (int)(EL_W / 4);
    conv_xy<<<dim3((n4x + 255)/256, 2), 256>>>(X, Y, X16, Y16, n4x);
    conv_w4<<<dim3((n4w + 255)/256, 4), 256>>>(Wq, Wk, Wv, Wo, W16, n4w);

    const int total64 = (int)((size_t)BB*NN*MM/64);
    pack_mask<<<(total64 + 255)/256, 256>>>(mask, mbits, total64);

    gemm_qkv<<<dim3(DD/128, RR/128, 3), 256, SMP>>>(
        X16, Y16, W16, bq, bk, bv, Q16, K16, V16);

    flash_mma<<<dim3(NN/128, BB*HH), 256, FLASH_SMEM>>>(
        mbits, P16, Q16, K16, V16, rowsum, T16);

    // fork: norm_beta (HBM-bound) on s2  ||  gemm_o (tensor-bound) on main
    cudaEventRecord(ev1, 0);
    cudaStreamWaitEvent(s2, ev1, 0);
    norm_beta<<<BB*HH*NN, 256, 0, s2>>>(P16, rowsum, beta);
    cudaEventRecord(ev2, s2);

    gemm_o<<<dim3(DD/128, RR/128), 256, SMP>>>(T16, W16 + 3*EL_W, bo, out);

    cudaStreamWaitEvent((cudaStream_t)0, ev2, 0);
}

// round 14
// speedup vs baseline: 1.0302x; 1.0302x over previous
#include <cuda_runtime.h>
#include <cuda_fp16.h>
#include <stdint.h>

#define BB 4
#define NN 2048
#define MM 2048
#define DD 1024
#define HH 16
#define DKK 64
#define RR (BB*NN)

#define EL_X ((size_t)RR*DD)     // 8,388,608
#define EL_W ((size_t)DD*DD)     // 1,048,576

// fp16 arena: 0 X, 1 Y, 2 Q, 3 K, 4 V, 5 T (EL_X each), then 4 weights (EL_W)
__device__ __half g_f16[6*EL_X + 4*EL_W];
__device__ __half g_p16[(size_t)BB*HH*NN*MM];          // unnormalized exp scratch
__device__ float g_rowsum[(size_t)BB*HH*NN];
__device__ uint64_t g_mbits[(size_t)BB*NN*MM/64];      // packed mask bits
__device__ float g_beta_scratch[(size_t)BB*HH*NN*MM];  // fallback only

extern __shared__ char smraw[];

// ---------------------------------------------------------------------------
__device__ __forceinline__ uint32_t smem_u32(const void* p) {
    uint32_t a;
    asm("{ .reg .u64 t; cvta.to.shared.u64 t, %1; cvt.u32.u64 %0, t; }"
        : "=r"(a) : "l"(p));
    return a;
}

#define CP16(s, g) \
    asm volatile("cp.async.cg.shared.global [%0], [%1], 16;" :: "r"(s), "l"(g))
#define CPC() asm volatile("cp.async.commit_group;" ::: "memory")
#define CPW(n) asm volatile("cp.async.wait_group %0;" :: "n"(n) : "memory")

#define LDSM4(r, addr) \
    asm volatile("ldmatrix.sync.aligned.m8n8.x4.shared.b16 {%0,%1,%2,%3}, [%4];" \
        : "=r"((r)[0]), "=r"((r)[1]), "=r"((r)[2]), "=r"((r)[3]) : "r"(addr))
#define LDSM4T(r, addr) \
    asm volatile("ldmatrix.sync.aligned.m8n8.x4.trans.shared.b16 {%0,%1,%2,%3}, [%4];" \
        : "=r"((r)[0]), "=r"((r)[1]), "=r"((r)[2]), "=r"((r)[3]) : "r"(addr))

#define MMA_F16(d, a, b0, b1) \
    asm volatile("mma.sync.aligned.m16n8k16.row.col.f32.f16.f16.f32 " \
        "{%0,%1,%2,%3}, {%4,%5,%6,%7}, {%8,%9}, {%0,%1,%2,%3};" \
        : "+f"((d)[0]), "+f"((d)[1]), "+f"((d)[2]), "+f"((d)[3]) \
        : "r"((a)[0]), "r"((a)[1]), "r"((a)[2]), "r"((a)[3]), "r"(b0), "r"(b1))

__device__ __forceinline__ uint32_t pack16(float x, float y) {
    __half2 v = __floats2half2_rn(x, y);
    return *(uint32_t*)&v;
}

// ---------------------------------------------------------------------------
// fp32 -> fp16 conversions
// ---------------------------------------------------------------------------
__global__ void __launch_bounds__(256) conv_xy(const float* __restrict__ sx,
                                               const float* __restrict__ sy,
                                               __half* __restrict__ dx,
                                               __half* __restrict__ dy, int n4)
{
    int i = blockIdx.x * blockDim.x + threadIdx.x;
    if (i >= n4) return;
    const float* s = blockIdx.y ? sy : sx;
    uint32_t* hp = (uint32_t*)(blockIdx.y ? dy : dx);
    float4 v = ((const float4*)s)[i];
    hp[2*i]   = pack16(v.x, v.y);
    hp[2*i+1] = pack16(v.z, v.w);
}

__global__ void __launch_bounds__(256) conv_w4(const float* __restrict__ s0,
                                               const float* __restrict__ s1,
                                               const float* __restrict__ s2,
                                               const float* __restrict__ s3,
                                               __half* __restrict__ dbase, int n4)
{
    int i = blockIdx.x * blockDim.x + threadIdx.x;
    if (i >= n4) return;
    const float* srcs[4] = {s0, s1, s2, s3};
    const float* s = srcs[blockIdx.y];
    uint32_t* hp = (uint32_t*)(dbase + (size_t)blockIdx.y * EL_W);
    float4 v = ((const float4*)s)[i];
    hp[2*i]   = pack16(v.x, v.y);
    hp[2*i+1] = pack16(v.z, v.w);
}

// pack mask int32 -> bits (bit set <=> mask==1 <=> masked out)
__global__ void __launch_bounds__(256) pack_mask(const int* __restrict__ mask,
                                                 uint64_t* __restrict__ bits,
                                                 int total64)
{
    int i = blockIdx.x * blockDim.x + threadIdx.x;
    if (i >= total64) return;
    const int4* src = (const int4*)(mask + (size_t)i * 64);
    uint64_t w = 0;
    #pragma unroll
    for (int q = 0; q < 16; q++) {
        int4 v = src[q];
        w |= (uint64_t)(v.x == 1) << (q*4 + 0);
        w |= (uint64_t)(v.y == 1) << (q*4 + 1);
        w |= (uint64_t)(v.z == 1) << (q*4 + 2);
        w |= (uint64_t)(v.w == 1) << (q*4 + 3);
    }
    bits[i] = w;
}

// ---------------------------------------------------------------------------
// GEMM core (device inline): C(128x128) = A @ W^T + bias, fp16 in, fp32 acc.
// ---------------------------------------------------------------------------
template<int OUTMODE>
__device__ __forceinline__ void gemm_body(
    const __half* __restrict__ A,
    const __half* __restrict__ W,
    const float* __restrict__ bias,
    float* __restrict__ outF,
    __half* __restrict__ outH,
    int row0, int col0)
{
    __half* sm = (__half*)smraw;
    const int tid  = threadIdx.x;
    const int lane = tid & 31;
    const int wid  = tid >> 5;
    const int wm   = wid & 3;
    const int wn   = wid >> 2;
    const uint32_t sbase = smem_u32(sm);

    float acc[2][8][4];
    #pragma unroll
    for (int i = 0; i < 2; i++)
        #pragma unroll
        for (int j = 0; j < 8; j++)
            #pragma unroll
            for (int q = 0; q < 4; q++) acc[i][j][q] = 0.f;

    #define ISSUE(t) do {                                                      \
        const int k0 = (t) << 6;                                               \
        const uint32_t sA = sbase + (((t) & 1) * 9216) * 2;                    \
        const uint32_t sW = sbase + (18432 + ((t) & 1) * 9216) * 2;            \
        _Pragma("unroll")                                                      \
        for (int i_ = 0; i_ < 4; i_++) {                                       \
            int idx = tid + i_ * 256;                                          \
            int r = idx >> 3, ch = idx & 7;                                    \
            CP16(sA + (r * 72 + ch * 8) * 2,                                   \
                 A + (size_t)(row0 + r) * DD + k0 + ch * 8);                   \
            CP16(sW + (r * 72 + ch * 8) * 2,                                   \
                 W + (size_t)(col0 + r) * DD + k0 + ch * 8);                   \
        }                                                                      \
        CPC();                                                                 \
    } while (0)

    ISSUE(0);
    for (int t = 0; t < 16; t++) {
        if (t + 1 < 16) { ISSUE(t + 1); CPW(1); }
        else            { CPW(0); }
        __syncthreads();
        const uint32_t sA = sbase + ((t & 1) * 9216) * 2;
        const uint32_t sW = sbase + (18432 + (t & 1) * 9216) * 2;
        #pragma unroll
        for (int ks = 0; ks < 4; ks++) {
            uint32_t a[2][4], bq[4][4];
            #pragma unroll
            for (int i = 0; i < 2; i++)
                LDSM4(a[i], sA + ((wm*32 + i*16 + (lane & 15)) * 72
                                  + ks*16 + (lane >> 4) * 8) * 2);
            #pragma unroll
            for (int jj = 0; jj < 4; jj++)
                LDSM4(bq[jj], sW + ((wn*64 + jj*16 + (lane & 15)) * 72
                                    + ks*16 + (lane >> 4) * 8) * 2);
            #pragma unroll
            for (int i = 0; i < 2; i++)
                #pragma unroll
                for (int j = 0; j < 8; j++) {
                    const int jj = j >> 1;
                    uint32_t b0 = (j & 1) ? bq[jj][1] : bq[jj][0];
                    uint32_t b1 = (j & 1) ? bq[jj][3] : bq[jj][2];
                    MMA_F16(acc[i][j], a[i], b0, b1);
                }
        }
        __syncthreads();
    }
    #undef ISSUE

    const int bb = row0 >> 11;
    #pragma unroll
    for (int i = 0; i < 2; i++) {
        const int r  = row0 + wm*32 + i*16 + (lane >> 2);
        const int n  = r & 2047;
        #pragma unroll
        for (int j = 0; j < 8; j++) {
            const int c = col0 + wn*64 + j*8 + (lane & 3)*2;
            const float b0v = __ldg(bias + c), b1v = __ldg(bias + c + 1);
            const float v00 = acc[i][j][0] + b0v, v01 = acc[i][j][1] + b1v;
            const float v10 = acc[i][j][2] + b0v, v11 = acc[i][j][3] + b1v;
            if (OUTMODE == 0) {
                *(float2*)(outF + (size_t)r * DD + c)       = make_float2(v00, v01);
                *(float2*)(outF + (size_t)(r + 8) * DD + c) = make_float2(v10, v11);
            } else {
                const int h = c >> 6, dk = c & 63;
                const size_t a0 = ((((size_t)bb*HH + h)*NN + n)      << 6) + dk;
                const size_t a1 = ((((size_t)bb*HH + h)*NN + (n+8))  << 6) + dk;
                *(uint32_t*)(outH + a0) = pack16(v00, v01);
                *(uint32_t*)(outH + a1) = pack16(v10, v11);
            }
        }
    }
}

// ---------------------------------------------------------------------------
// Q/K/V projections in ONE launch (measured -140us vs 3 launches).
// ---------------------------------------------------------------------------
__global__ void __launch_bounds__(256,2) gemm_qkv(
    const __half* __restrict__ X16, const __half* __restrict__ Y16,
    const __half* __restrict__ W16,
    const float* __restrict__ bq, const float* __restrict__ bk,
    const float* __restrict__ bv,
    __half* __restrict__ Q16, __half* __restrict__ K16, __half* __restrict__ V16)
{
    const int z = blockIdx.z;
    const __half* A   = (z == 0) ? X16 : Y16;
    const __half* W   = W16 + (size_t)z * EL_W;
    const float* bias = (z == 0) ? bq : ((z == 1) ? bk : bv);
    __half* outH      = (z == 0) ? Q16 : ((z == 1) ? K16 : V16);
    gemm_body<1>(A, W, bias, nullptr, outH,
                 blockIdx.y * 128, blockIdx.x * 128);
}

__global__ void __launch_bounds__(256,2) gemm_o(
    const __half* __restrict__ T16, const __half* __restrict__ Wo16,
    const float* __restrict__ bo, float* __restrict__ outF)
{
    gemm_body<0>(T16, Wo16, bo, outF, nullptr,
                 blockIdx.y * 128, blockIdx.x * 128);
}

// ---------------------------------------------------------------------------
// Fused flash middle — R12 version (occ=1, no reg cap; R13's 2-CTA diet spilled).
// smem: Q 0 (18432), K[2] 18432/36864, V[2] 55296/73728, P 92160 (stride 136).
// ---------------------------------------------------------------------------
#define FQ  0
#define FK(s) (18432 + (s)*18432)
#define FV(s) (55296 + (s)*18432)
#define FP    92160
#define FLASH_SMEM 126976

__global__ void __launch_bounds__(256,1) flash_mma(
    const uint64_t* __restrict__ mbits,
    __half* __restrict__ P16,
    const __half* __restrict__ Q,
    const __half* __restrict__ K,
    const __half* __restrict__ V,
    float* __restrict__ rowsum,
    __half* __restrict__ Wt)
{
    char* sm = smraw;
    __shared__ float srow[128];
    const int tid  = threadIdx.x;
    const int lane = tid & 31;
    const int wid  = tid >> 5;
    const int wm   = wid & 3;
    const int wn   = wid >> 2;
    const int z    = blockIdx.y;
    const int b    = z >> 4;
    const int h    = z & 15;
    const int n0   = blockIdx.x * 128;
    const uint32_t sb = smem_u32(sm);
    __half* smP = (__half*)(sm + FP);

    if (tid < 128) srow[tid] = 0.f;

    // ---- load Q tile (persistent)
    {
        const __half* q = Q + ((size_t)z*NN + n0) * DKK;
        #pragma unroll
        for (int i = 0; i < 4; i++) {
            int idx = tid + i * 256;
            int r = idx >> 3, ch = idx & 7;
            CP16(sb + FQ + (uint32_t)(r * 72 + ch * 8) * 2,
                 q + (size_t)r * DKK + ch * 8);
        }
    }

    #define FISSUE_KV(t) do {                                                  \
        const int st_ = (t) & 1;                                               \
        const __half* kp = K + ((size_t)z*MM + (t)*128) * DKK;                 \
        const __half* vp = V + ((size_t)z*MM + (t)*128) * DKK;                 \
        _Pragma("unroll")                                                      \
        for (int i_ = 0; i_ < 4; i_++) {                                       \
            int idx = tid + i_ * 256;                                          \
            int r = idx >> 3, ch = idx & 7;                                    \
            uint32_t off = (uint32_t)(r * 72 + ch * 8) * 2;                    \
            size_t go = (size_t)r * DKK + ch * 8;                              \
            CP16(sb + FK(st_) + off, kp + go);                                 \
            CP16(sb + FV(st_) + off, vp + go);                                 \
        }                                                                      \
        CPC();                                                                 \
    } while (0)

    FISSUE_KV(0);   // commits Q loads too (same group)

    float accO[8][4];
    #pragma unroll
    for (int j = 0; j < 8; j++)
        #pragma unroll
        for (int q = 0; q < 4; q++) accO[j][q] = 0.f;
    float rsum[4] = {0.f, 0.f, 0.f, 0.f};

    const float scl = 0.125f;
    const size_t prow = (size_t)z * NN + n0;

    for (int mt = 0; mt < 16; mt++) {
        const int st = mt & 1;
        CPW(0);
        __syncthreads();

        // ---- QK^T (single pass)
        float acc[2][8][4];
        #pragma unroll
        for (int i = 0; i < 2; i++)
            #pragma unroll
            for (int j = 0; j < 8; j++)
                #pragma unroll
                for (int q = 0; q < 4; q++) acc[i][j][q] = 0.f;

        #pragma unroll
        for (int ks = 0; ks < 4; ks++) {
            uint32_t a[2][4], bq[4][4];
            #pragma unroll
            for (int i = 0; i < 2; i++)
                LDSM4(a[i], sb + FQ + ((wm*32 + i*16 + (lane & 15)) * 72
                                       + ks*16 + (lane >> 4) * 8) * 2);
            #pragma unroll
            for (int jj = 0; jj < 4; jj++)
                LDSM4(bq[jj], sb + FK(st) + ((wn*64 + jj*16 + (lane & 15)) * 72
                                             + ks*16 + (lane >> 4) * 8) * 2);
            #pragma unroll
            for (int i = 0; i < 2; i++)
                #pragma unroll
                for (int j = 0; j < 8; j++) {
                    const int jj = j >> 1;
                    uint32_t b0 = (j & 1) ? bq[jj][1] : bq[jj][0];
                    uint32_t b1 = (j & 1) ? bq[jj][3] : bq[jj][2];
                    MMA_F16(acc[i][j], a[i], b0, b1);
                }
        }

        if (mt < 15) FISSUE_KV(mt + 1);   // overlap next K/V load with exp+PV

        // ---- exp epilogue with packed mask bits
        const int m0 = mt * 128;
        #pragma unroll
        for (int i = 0; i < 2; i++) {
            const int r0 = wm*32 + i*16 + (lane >> 2);
            const size_t rowg = (size_t)b*NN + n0 + r0;
            const uint64_t w0 = mbits[rowg*32       + mt*2 + wn];
            const uint64_t w1 = mbits[(rowg + 8)*32 + mt*2 + wn];
            #pragma unroll
            for (int j = 0; j < 8; j++) {
                const int cl = wn*64 + j*8 + (lane & 3)*2;
                const int p  = j*8 + (lane & 3)*2;
                float e00 = ((w0 >> p)     & 1) ? 0.f : __expf(acc[i][j][0] * scl);
                float e01 = ((w0 >> (p+1)) & 1) ? 0.f : __expf(acc[i][j][1] * scl);
                float e10 = ((w1 >> p)     & 1) ? 0.f : __expf(acc[i][j][2] * scl);
                float e11 = ((w1 >> (p+1)) & 1) ? 0.f : __expf(acc[i][j][3] * scl);
                rsum[i*2+0] += e00 + e01;
                rsum[i*2+1] += e10 + e11;
                *(__half2*)(smP + r0*136 + cl)     = __floats2half2_rn(e00, e01);
                *(__half2*)(smP + (r0+8)*136 + cl) = __floats2half2_rn(e10, e11);
            }
        }
        __syncthreads();

        // ---- P smem -> gmem scratch (coalesced)
        #pragma unroll
        for (int it = 0; it < 8; it++) {
            int idx = tid + it * 256;
            int r = idx >> 4, q = idx & 15;
            *(uint4*)(P16 + (prow + r) * MM + m0 + q*8) =
                *(const uint4*)(smP + r*136 + q*8);
        }

        // ---- O += P x V (single pass)
        #pragma unroll
        for (int ks = 0; ks < 8; ks++) {
            uint32_t a[4], bq[4][4];
            LDSM4(a, sb + FP + ((wid*16 + (lane & 15)) * 136
                                + ks*16 + (lane >> 4) * 8) * 2);
            #pragma unroll
            for (int jj = 0; jj < 4; jj++)
                LDSM4T(bq[jj], sb + FV(st) + ((ks*16 + ((lane >> 3) & 1)*8 + (lane & 7)) * 72
                                              + jj*16 + (lane >> 4) * 8) * 2);
            #pragma unroll
            for (int j = 0; j < 8; j++) {
                const int jj = j >> 1;
                uint32_t b0 = (j & 1) ? bq[jj][2] : bq[jj][0];
                uint32_t b1 = (j & 1) ? bq[jj][3] : bq[jj][1];
                MMA_F16(accO[j], a, b0, b1);
            }
        }
        // loop-top __syncthreads() protects P & V buffers
    }
    #undef FISSUE_KV

    // ---- rowsum reduce
    #pragma unroll
    for (int k = 0; k < 4; k++) {
        rsum[k] += __shfl_xor_sync(0xffffffffu, rsum[k], 1);
        rsum[k] += __shfl_xor_sync(0xffffffffu, rsum[k], 2);
    }
    __syncthreads();
    if ((lane & 3) == 0) {
        #pragma unroll
        for (int k = 0; k < 4; k++) {
            const int rl = wm*32 + (k >> 1)*16 + (k & 1)*8 + (lane >> 2);
            atomicAdd(&srow[rl], rsum[k]);
        }
    }
    __syncthreads();
    if (tid < 128) rowsum[prow + tid] = srow[tid];

    // ---- normalize O, write wt (b,n,h,dk) fp16
    const int rl = wid*16 + (lane >> 2);
    const float inv0 = 1.0f / srow[rl];
    const float inv1 = 1.0f / srow[rl + 8];
    const int n = n0 + rl;
    #pragma unroll
    for (int j = 0; j < 8; j++) {
        const int dk = j*8 + (lane & 3)*2;
        const size_t a0 = ((((size_t)b*NN + n)     * HH + h) << 6) + dk;
        const size_t a1 = ((((size_t)b*NN + n + 8) * HH + h) << 6) + dk;
        *(uint32_t*)(Wt + a0) = pack16(accO[j][0]*inv0, accO[j][1]*inv0);
        *(uint32_t*)(Wt + a1) = pack16(accO[j][2]*inv1, accO[j][3]*inv1);
    }
}

// ---------------------------------------------------------------------------
// beta = P16 * (1/rowsum), fp32 out. One block per row (high occupancy, 0 smem).
// ---------------------------------------------------------------------------
__global__ void __launch_bounds__(256) norm_beta(const __half* __restrict__ P16,
                                                 const float* __restrict__ rowsum,
                                                 float* __restrict__ beta)
{
    const size_t row = blockIdx.x;
    const float inv = 1.0f / __ldg(rowsum + row);
    const __half* src = P16 + row * MM;
    float* dst = beta + row * MM;
    const int t = threadIdx.x;
    uint4 v = *(const uint4*)(src + t * 8);
    const __half2* h2 = (const __half2*)&v;
    float4 o0, o1;
    float2 f;
    f = __half22float2(h2[0]); o0.x = f.x*inv; o0.y = f.y*inv;
    f = __half22float2(h2[1]); o0.z = f.x*inv; o0.w = f.y*inv;
    f = __half22float2(h2[2]); o1.x = f.x*inv; o1.y = f.y*inv;
    f = __half22float2(h2[3]); o1.z = f.x*inv; o1.w = f.y*inv;
    *(float4*)(dst + t*8)     = o0;
    *(float4*)(dst + t*8 + 4) = o1;
}

// ============================================================================
extern "C" void kernel_launch(void* const* d_in, const int* in_sizes, int n_in,
                              void* d_out, int out_size)
{
    const float* X    = (const float*)d_in[0];
    const float* Y    = (const float*)d_in[1];
    const int*   mask = (const int*)  d_in[2];
    const float* Wq   = (const float*)d_in[3];
    const float* bq   = (const float*)d_in[4];
    const float* Wk   = (const float*)d_in[5];
    const float* bk   = (const float*)d_in[6];
    const float* Wv   = (const float*)d_in[7];
    const float* bv   = (const float*)d_in[8];
    const float* Wo   = (const float*)d_in[9];
    const float* bo   = (const float*)d_in[10];
    float* out = (float*)d_out;

    const size_t ATTN = (size_t)BB * NN * DD;
    const size_t BETA = (size_t)BB * HH * NN * MM;

    void *fp_, *bsp_, *rsp_, *p16_, *mb_;
    cudaGetSymbolAddress(&fp_, g_f16);
    cudaGetSymbolAddress(&bsp_, g_beta_scratch);
    cudaGetSymbolAddress(&rsp_, g_rowsum);
    cudaGetSymbolAddress(&p16_, g_p16);
    cudaGetSymbolAddress(&mb_, g_mbits);
    __half* f16 = (__half*)fp_;
    __half* P16 = (__half*)p16_;
    float* rowsum = (float*)rsp_;
    uint64_t* mbits = (uint64_t*)mb_;

    __half* X16 = f16 + 0*EL_X;
    __half* Y16 = f16 + 1*EL_X;
    __half* Q16 = f16 + 2*EL_X;
    __half* K16 = f16 + 3*EL_X;
    __half* V16 = f16 + 4*EL_X;
    __half* T16 = f16 + 5*EL_X;
    __half* W16 = f16 + 6*EL_X;      // 4 weights contiguous: Wq,Wk,Wv,Wo

    float* beta = ((size_t)out_size >= ATTN + BETA) ? (out + ATTN)
                                                    : (float*)bsp_;

    // side stream + events created once, on the first (non-captured) call
    static cudaStream_t s2 = nullptr;
    static cudaEvent_t ev0 = nullptr, ev1 = nullptr, ev2 = nullptr;
    if (!s2) {
        cudaStreamCreateWithFlags(&s2, cudaStreamNonBlocking);
        cudaEventCreateWithFlags(&ev0, cudaEventDisableTiming);
        cudaEventCreateWithFlags(&ev1, cudaEventDisableTiming);
        cudaEventCreateWithFlags(&ev2, cudaEventDisableTiming);
    }

    const int SMP = 73728;
    cudaFuncSetAttribute(gemm_qkv,  cudaFuncAttributeMaxDynamicSharedMemorySize, SMP);
    cudaFuncSetAttribute(gemm_o,    cudaFuncAttributeMaxDynamicSharedMemorySize, SMP);
    cudaFuncSetAttribute(flash_mma, cudaFuncAttributeMaxDynamicSharedMemorySize, FLASH_SMEM);

    const int n4x = (int)(EL_X / 4);
    const int n4w = (int)(EL_W / 4);
    const int total64 = (int)((size_t)BB*NN*MM/64);

    // fork prep: pack_mask on s2 concurrent with convs on main.
    // s2 must be ordered after graph entry: chain it off the main stream.
    cudaEventRecord(ev0, 0);
    cudaStreamWaitEvent(s2, ev0, 0);
    pack_mask<<<(total64 + 255)/256, 256, 0, s2>>>(mask, mbits, total64);
    cudaEventRecord(ev1, s2);

    conv_xy<<<dim3((n4x + 255)/256, 2), 256>>>(X, Y, X16, Y16, n4x);
    conv_w4<<<dim3((n4w + 255)/256, 4), 256>>>(Wq, Wk, Wv, Wo, W16, n4w);

    gemm_qkv<<<dim3(DD/128, RR/128, 3), 256, SMP>>>(
        X16, Y16, W16, bq, bk, bv, Q16, K16, V16);

    // flash needs mbits (s2) + QKV (main)
    cudaStreamWaitEvent((cudaStream_t)0, ev1, 0);
    flash_mma<<<dim3(NN/128, BB*HH), 256, FLASH_SMEM>>>(
        mbits, P16, Q16, K16, V16, rowsum, T16);

    // fork: norm_beta (HBM-bound) on s2  ||  gemm_o (tensor-bound) on main
    cudaEventRecord(ev0, 0);
    cudaStreamWaitEvent(s2, ev0, 0);
    norm_beta<<<BB*HH*NN, 256, 0, s2>>>(P16, rowsum, beta);
    cudaEventRecord(ev2, s2);

    gemm_o<<<dim3(DD/128, RR/128), 256, SMP>>>(T16, W16 + 3*EL_W, bo, out);

    cudaStreamWaitEvent((cudaStream_t)0, ev2, 0);
}